// round 2
// baseline (speedup 1.0000x reference)
#include <cuda_runtime.h>

#define BATCH   256
#define INDIM   159
#define MDIM    93
#define MATEL   2976
#define LINDIM  (MDIM + MATEL)   /* 3069 */
#define KPATH   64
#define SIGDIM  340

__device__ float g_lin[BATCH * LINDIM];
__device__ float g_newV[BATCH * MDIM * KPATH];
__device__ float g_sigp[2 * BATCH * SIGDIM];

// ---------------------------------------------------------------------------
// Kernel 1: lin[b, 0:93]   = x[b] @ W_mean^T + b_mean
//           lin[b, 93:3069]= x[b] @ W_cov^T  + b_cov
// Tiled: each block handles 8 batches x 128 rows.
// ---------------------------------------------------------------------------
__global__ void __launch_bounds__(128) k_linear(
    const float* __restrict__ x,
    const float* __restrict__ Wm, const float* __restrict__ bm,
    const float* __restrict__ Wc, const float* __restrict__ bc)
{
    __shared__ float xs[8][INDIM];
    __shared__ float Ws[128][33];
    const int tid = threadIdx.x;
    const int b0  = blockIdx.y * 8;
    const int r0  = blockIdx.x * 128;

    for (int e = tid; e < 8 * INDIM; e += 128) {
        int bb = e / INDIM, c = e % INDIM;
        xs[bb][c] = x[(b0 + bb) * INDIM + c];
    }

    const int r = r0 + tid;
    float bias = 0.f;
    if (r < LINDIM) bias = (r < MDIM) ? bm[r] : bc[r - MDIM];
    float acc[8];
#pragma unroll
    for (int bb = 0; bb < 8; bb++) acc[bb] = bias;

    for (int ct = 0; ct < INDIM; ct += 32) {
        const int cn = min(32, INDIM - ct);
        __syncthreads();
        for (int e = tid; e < 128 * 32; e += 128) {
            int rr = e >> 5, cc = e & 31;
            int rg = r0 + rr;
            float w = 0.f;
            if (rg < LINDIM && cc < cn)
                w = (rg < MDIM) ? Wm[rg * INDIM + ct + cc]
                                : Wc[(rg - MDIM) * INDIM + ct + cc];
            Ws[rr][cc] = w;
        }
        __syncthreads();
        for (int cc = 0; cc < cn; cc++) {
            float w = Ws[tid][cc];
#pragma unroll
            for (int bb = 0; bb < 8; bb++)
                acc[bb] = fmaf(w, xs[bb][ct + cc], acc[bb]);
        }
    }
    if (r < LINDIM) {
#pragma unroll
        for (int bb = 0; bb < 8; bb++)
            g_lin[(b0 + bb) * LINDIM + r] = acc[bb];
    }
}

// ---------------------------------------------------------------------------
// Kernel 2: newV[b,i,k] = mean[b,i] + sum_{j in band} M[b,i,j] * eps[b,j,k]
// Band structure (alpha='full'): row i = 3X+tr has nonzeros at cols 3y+tc
// for y<=X, tc<=tr, with value sqrtCov at flat index
//   (31d - d(d-1)/2 + y)*6 + tr(tr+1)/2 + tc,  d = X - y.
// One block per batch element; eps + cov + mean staged in shared.
// ---------------------------------------------------------------------------
__global__ void __launch_bounds__(256) k_newv(const float* __restrict__ eps)
{
    __shared__ float eps_s[MDIM * KPATH];   // 23808 B
    __shared__ float cov_s[MATEL];          // 11904 B
    __shared__ float mean_s[MDIM];
    const int b = blockIdx.x, tid = threadIdx.x;
    const float* lin = g_lin + b * LINDIM;

    for (int e = tid; e < MDIM * KPATH; e += 256)
        eps_s[e] = eps[b * MDIM * KPATH + e];
    for (int e = tid; e < MATEL; e += 256) cov_s[e] = lin[MDIM + e];
    for (int e = tid; e < MDIM; e += 256)  mean_s[e] = lin[e];
    __syncthreads();

    const int k  = tid & 63;
    const int i0 = tid >> 6;   // 0..3
    for (int i = i0; i < MDIM; i += 4) {
        const int X = i / 3, tr = i % 3;
        const int tbase = tr * (tr + 1) / 2;
        float acc = mean_s[i];
        for (int y = 0; y <= X; y++) {
            const int d = X - y;
            const int blk = (31 * d - (d * (d - 1)) / 2 + y) * 6 + tbase;
#pragma unroll
            for (int tc = 0; tc < 3; tc++) {
                if (tc <= tr)
                    acc = fmaf(cov_s[blk + tc], eps_s[(y * 3 + tc) * KPATH + k], acc);
            }
        }
        g_newV[(b * MDIM + i) * KPATH + k] = acc;
    }
}

// ---------------------------------------------------------------------------
// Kernel 3: signatures. 4 threads per path (slice leading tensor index),
// 32 paths (half of K) per 128-thread block; grid = 2*BATCH.
// ---------------------------------------------------------------------------
struct SigState {
    float S1;
    float S2[4];
    float S3[16];
    float S4[64];
};

__device__ __forceinline__ void chen_step(SigState& s, const float d[4], float da)
{
    float hd[4], h2[16];
#pragma unroll
    for (int c = 0; c < 4; c++) hd[c] = 0.5f * d[c];
#pragma unroll
    for (int c = 0; c < 4; c++)
#pragma unroll
        for (int e = 0; e < 4; e++) h2[c * 4 + e] = hd[c] * d[e];

    // level-4: S4 += S3 (x) e1  +  (S2 + (S1 + da/4)/3 * d) (x) h2
    const float g4 = fmaf(0.25f, da, s.S1) * (1.f / 3.f);
    float r[4];
#pragma unroll
    for (int bq = 0; bq < 4; bq++) r[bq] = fmaf(g4, d[bq], s.S2[bq]);
#pragma unroll
    for (int bq = 0; bq < 4; bq++) {
#pragma unroll
        for (int c = 0; c < 4; c++) {
            const float s3v = s.S3[bq * 4 + c];
#pragma unroll
            for (int e = 0; e < 4; e++) {
                float v = s.S4[bq * 16 + c * 4 + e];
                v = fmaf(s3v, d[e], v);
                v = fmaf(r[bq], h2[c * 4 + e], v);
                s.S4[bq * 16 + c * 4 + e] = v;
            }
        }
    }
    // level-3: S3 += S2 (x) e1 + (S1 + da/3) * h2
    const float g3 = fmaf(1.f / 3.f, da, s.S1);
#pragma unroll
    for (int bq = 0; bq < 4; bq++) {
        const float s2v = s.S2[bq];
#pragma unroll
        for (int c = 0; c < 4; c++) {
            float v = s.S3[bq * 4 + c];
            v = fmaf(s2v, d[c], v);
            v = fmaf(g3, h2[bq * 4 + c], v);
            s.S3[bq * 4 + c] = v;
        }
    }
    // level-2: S2 += (S1 + da/2) * d
    const float g2 = fmaf(0.5f, da, s.S1);
#pragma unroll
    for (int bq = 0; bq < 4; bq++) s.S2[bq] = fmaf(g2, d[bq], s.S2[bq]);
    s.S1 += da;
}

__device__ __forceinline__ float wred8(float v)
{
    v += __shfl_down_sync(0xffffffffu, v, 16);
    v += __shfl_down_sync(0xffffffffu, v, 8);
    v += __shfl_down_sync(0xffffffffu, v, 4);
    return v;
}

__global__ void __launch_bounds__(128) k_sig(const float* __restrict__ x)
{
    __shared__ float xs[INDIM];
    __shared__ float nvs[MDIM * 32];
    __shared__ float red[4 * SIGDIM];

    const int blk = blockIdx.x;
    const int b = blk >> 1, h = blk & 1;
    const int tid = threadIdx.x;

    for (int e = tid; e < INDIM; e += 128) xs[e] = x[b * INDIM + e];
    for (int e = tid; e < MDIM * 32; e += 128) {
        int i = e >> 5, kk = e & 31;
        nvs[e] = g_newV[(b * MDIM + i) * KPATH + h * 32 + kk];
    }
    __syncthreads();

    const int kk = tid >> 2;   // path within block (0..31)
    const int a  = tid & 3;    // tensor slice

    SigState s;
    s.S1 = 0.f;
#pragma unroll
    for (int i = 0; i < 4; i++) s.S2[i] = 0.f;
#pragma unroll
    for (int i = 0; i < 16; i++) s.S3[i] = 0.f;
#pragma unroll
    for (int i = 0; i < 64; i++) s.S4[i] = 0.f;

    // path: old0, new0, old1, new1, ..., old30, new30, old31
    float p0 = xs[0], p1 = xs[1], p2 = xs[2], p3 = xs[96];
    for (int m = 0; m < 31; m++) {
        // old m -> new m
        float q0 = nvs[(3 * m + 0) * 32 + kk];
        float q1 = nvs[(3 * m + 1) * 32 + kk];
        float q2 = nvs[(3 * m + 2) * 32 + kk];
        float qt = xs[128 + m];
        {
            float d[4] = { q0 - p0, q1 - p1, q2 - p2, qt - p3 };
            float da = (a == 0) ? d[0] : (a == 1) ? d[1] : (a == 2) ? d[2] : d[3];
            chen_step(s, d, da);
        }
        p0 = q0; p1 = q1; p2 = q2; p3 = qt;
        // new m -> old m+1
        q0 = xs[3 * (m + 1) + 0];
        q1 = xs[3 * (m + 1) + 1];
        q2 = xs[3 * (m + 1) + 2];
        qt = xs[96 + m + 1];
        {
            float d[4] = { q0 - p0, q1 - p1, q2 - p2, qt - p3 };
            float da = (a == 0) ? d[0] : (a == 1) ? d[1] : (a == 2) ? d[2] : d[3];
            chen_step(s, d, da);
        }
        p0 = q0; p1 = q1; p2 = q2; p3 = qt;
    }

    // per-path norms (reduce slice partials over the 4 lanes of this path)
    float n1 = s.S1 * s.S1;
    float n2 = 0.f, n3 = 0.f, n4 = 0.f;
#pragma unroll
    for (int i = 0; i < 4; i++)  n2 = fmaf(s.S2[i], s.S2[i], n2);
#pragma unroll
    for (int i = 0; i < 16; i++) n3 = fmaf(s.S3[i], s.S3[i], n3);
#pragma unroll
    for (int i = 0; i < 64; i++) n4 = fmaf(s.S4[i], s.S4[i], n4);
#pragma unroll
    for (int msk = 1; msk <= 2; msk <<= 1) {
        n1 += __shfl_xor_sync(0xffffffffu, n1, msk);
        n2 += __shfl_xor_sync(0xffffffffu, n2, msk);
        n3 += __shfl_xor_sync(0xffffffffu, n3, msk);
        n4 += __shfl_xor_sync(0xffffffffu, n4, msk);
    }
    const float norm2 = 1.f + n1 + n2 + n3 + n4;
    const float psi = (norm2 <= 4.f) ? norm2 : (8.f - 16.f / norm2);
    float lo = 0.f, hi = 1.f;
    for (int it = 0; it < 40; it++) {
        float mid = 0.5f * (lo + hi);
        float m2 = mid * mid, m4 = m2 * m2;
        float val = 1.f + m2 * n1 + m4 * n2 + (m4 * m2) * n3 + (m4 * m4) * n4;
        bool pos = val > psi;
        hi = pos ? mid : hi;
        lo = pos ? lo : mid;
    }
    const float lam = 0.5f * (lo + hi);
    const float l2 = lam * lam, l3 = l2 * lam, l4 = l2 * l2;
    s.S1 *= lam;
#pragma unroll
    for (int i = 0; i < 4; i++)  s.S2[i] *= l2;
#pragma unroll
    for (int i = 0; i < 16; i++) s.S3[i] *= l3;
#pragma unroll
    for (int i = 0; i < 64; i++) s.S4[i] *= l4;

    // reduce over the 8 paths of each warp; lanes 0..3 (= slice a) hold sums
    const int w = tid >> 5;
    const int lane = tid & 31;
    float v;
    v = wred8(s.S1);
    if (lane < 4) red[w * SIGDIM + a] = v;
#pragma unroll
    for (int j = 0; j < 4; j++) {
        v = wred8(s.S2[j]);
        if (lane < 4) red[w * SIGDIM + 4 + a * 4 + j] = v;
    }
#pragma unroll
    for (int j = 0; j < 16; j++) {
        v = wred8(s.S3[j]);
        if (lane < 4) red[w * SIGDIM + 20 + a * 16 + j] = v;
    }
#pragma unroll
    for (int j = 0; j < 64; j++) {
        v = wred8(s.S4[j]);
        if (lane < 4) red[w * SIGDIM + 84 + a * 64 + j] = v;
    }
    __syncthreads();
    for (int e = tid; e < SIGDIM; e += 128) {
        float sum = red[e] + red[SIGDIM + e] + red[2 * SIGDIM + e] + red[3 * SIGDIM + e];
        g_sigp[blk * SIGDIM + e] = sum;
    }
}

// ---------------------------------------------------------------------------
// Kernel 4: expected signature -> logits -> log_softmax
// ---------------------------------------------------------------------------
__global__ void __launch_bounds__(256) k_final(
    const float* __restrict__ Wf, const float* __restrict__ bf,
    float* __restrict__ out)
{
    const int b = threadIdx.x;
    float logit[10];
#pragma unroll
    for (int c = 0; c < 10; c++) logit[c] = bf[c];
    for (int sidx = 0; sidx < SIGDIM; sidx++) {
        float sv = (g_sigp[(2 * b) * SIGDIM + sidx] + g_sigp[(2 * b + 1) * SIGDIM + sidx])
                   * (1.f / 64.f);
#pragma unroll
        for (int c = 0; c < 10; c++)
            logit[c] = fmaf(sv, Wf[c * SIGDIM + sidx], logit[c]);
    }
    float mx = logit[0];
#pragma unroll
    for (int c = 1; c < 10; c++) mx = fmaxf(mx, logit[c]);
    float se = 0.f;
#pragma unroll
    for (int c = 0; c < 10; c++) se += expf(logit[c] - mx);
    const float lse = mx + logf(se);
#pragma unroll
    for (int c = 0; c < 10; c++) out[b * 10 + c] = logit[c] - lse;
}

// ---------------------------------------------------------------------------
extern "C" void kernel_launch(void* const* d_in, const int* in_sizes, int n_in,
                              void* d_out, int out_size)
{
    const float* x   = (const float*)d_in[0];
    const float* Wm  = (const float*)d_in[1];
    const float* bm  = (const float*)d_in[2];
    const float* Wc  = (const float*)d_in[3];
    const float* bc  = (const float*)d_in[4];
    const float* Wf  = (const float*)d_in[5];
    const float* bf  = (const float*)d_in[6];
    const float* eps = (const float*)d_in[7];
    float* out = (float*)d_out;

    k_linear<<<dim3(24, 32), 128>>>(x, Wm, bm, Wc, bc);
    k_newv<<<BATCH, 256>>>(eps);
    k_sig<<<2 * BATCH, 128>>>(x);
    k_final<<<1, 256>>>(Wf, bf, out);
}

// round 3
// speedup vs baseline: 1.4353x; 1.4353x over previous
#include <cuda_runtime.h>

#define BATCH   256
#define INDIM   159
#define MDIM    93
#define MATEL   2976
#define LINDIM  (MDIM + MATEL)   /* 3069 */
#define KPATH   64
#define SIGDIM  340

__device__ float g_lin[BATCH * LINDIM];
__device__ float g_newV[BATCH * MDIM * KPATH];
__device__ float g_sigp[2 * BATCH * SIGDIM];

// ---------------------------------------------------------------------------
// Kernel 1: lin[b, 0:93]   = x[b] @ W_mean^T + b_mean
//           lin[b, 93:3069]= x[b] @ W_cov^T  + b_cov
// Tiled: each block handles 8 batches x 128 rows.
// ---------------------------------------------------------------------------
__global__ void __launch_bounds__(128) k_linear(
    const float* __restrict__ x,
    const float* __restrict__ Wm, const float* __restrict__ bm,
    const float* __restrict__ Wc, const float* __restrict__ bc)
{
    __shared__ float xs[8][INDIM];
    __shared__ float Ws[128][33];
    const int tid = threadIdx.x;
    const int b0  = blockIdx.y * 8;
    const int r0  = blockIdx.x * 128;

    for (int e = tid; e < 8 * INDIM; e += 128) {
        int bb = e / INDIM, c = e % INDIM;
        xs[bb][c] = x[(b0 + bb) * INDIM + c];
    }

    const int r = r0 + tid;
    float bias = 0.f;
    if (r < LINDIM) bias = (r < MDIM) ? bm[r] : bc[r - MDIM];
    float acc[8];
#pragma unroll
    for (int bb = 0; bb < 8; bb++) acc[bb] = bias;

    for (int ct = 0; ct < INDIM; ct += 32) {
        const int cn = min(32, INDIM - ct);
        __syncthreads();
        for (int e = tid; e < 128 * 32; e += 128) {
            int rr = e >> 5, cc = e & 31;
            int rg = r0 + rr;
            float w = 0.f;
            if (rg < LINDIM && cc < cn)
                w = (rg < MDIM) ? Wm[rg * INDIM + ct + cc]
                                : Wc[(rg - MDIM) * INDIM + ct + cc];
            Ws[rr][cc] = w;
        }
        __syncthreads();
        for (int cc = 0; cc < cn; cc++) {
            float w = Ws[tid][cc];
#pragma unroll
            for (int bb = 0; bb < 8; bb++)
                acc[bb] = fmaf(w, xs[bb][ct + cc], acc[bb]);
        }
    }
    if (r < LINDIM) {
#pragma unroll
        for (int bb = 0; bb < 8; bb++)
            g_lin[(b0 + bb) * LINDIM + r] = acc[bb];
    }
}

// ---------------------------------------------------------------------------
// Kernel 2: newV[b,i,k] = mean[b,i] + sum_{j in band} M[b,i,j] * eps[b,j,k]
// Band structure (alpha='full'): row i = 3X+tr has nonzeros at cols 3y+tc
// for y<=X, tc<=tr, with value sqrtCov at flat index
//   (31d - d(d-1)/2 + y)*6 + tr(tr+1)/2 + tc,  d = X - y.
// One block per batch element; eps + cov + mean staged in shared.
// ---------------------------------------------------------------------------
__global__ void __launch_bounds__(256) k_newv(const float* __restrict__ eps)
{
    __shared__ float eps_s[MDIM * KPATH];   // 23808 B
    __shared__ float cov_s[MATEL];          // 11904 B
    __shared__ float mean_s[MDIM];
    const int b = blockIdx.x, tid = threadIdx.x;
    const float* lin = g_lin + b * LINDIM;

    for (int e = tid; e < MDIM * KPATH; e += 256)
        eps_s[e] = eps[b * MDIM * KPATH + e];
    for (int e = tid; e < MATEL; e += 256) cov_s[e] = lin[MDIM + e];
    for (int e = tid; e < MDIM; e += 256)  mean_s[e] = lin[e];
    __syncthreads();

    const int k  = tid & 63;
    const int i0 = tid >> 6;   // 0..3
    for (int i = i0; i < MDIM; i += 4) {
        const int X = i / 3, tr = i % 3;
        const int tbase = tr * (tr + 1) / 2;
        float acc = mean_s[i];
        for (int y = 0; y <= X; y++) {
            const int d = X - y;
            const int blk = (31 * d - (d * (d - 1)) / 2 + y) * 6 + tbase;
#pragma unroll
            for (int tc = 0; tc < 3; tc++) {
                if (tc <= tr)
                    acc = fmaf(cov_s[blk + tc], eps_s[(y * 3 + tc) * KPATH + k], acc);
            }
        }
        g_newV[(b * MDIM + i) * KPATH + k] = acc;
    }
}

// ---------------------------------------------------------------------------
// Kernel 3: signatures. 4 threads per path (slice leading tensor index),
// 32 paths (half of K) per 128-thread block; grid = 2*BATCH.
// ---------------------------------------------------------------------------
struct SigState {
    float S1;
    float S2[4];
    float S3[16];
    float S4[64];
};

__device__ __forceinline__ void chen_step(SigState& s, const float d[4], float da)
{
    float hd[4], h2[16];
#pragma unroll
    for (int c = 0; c < 4; c++) hd[c] = 0.5f * d[c];
#pragma unroll
    for (int c = 0; c < 4; c++)
#pragma unroll
        for (int e = 0; e < 4; e++) h2[c * 4 + e] = hd[c] * d[e];

    // level-4: S4 += S3 (x) e1  +  (S2 + (S1 + da/4)/3 * d) (x) h2
    const float g4 = fmaf(0.25f, da, s.S1) * (1.f / 3.f);
    float r[4];
#pragma unroll
    for (int bq = 0; bq < 4; bq++) r[bq] = fmaf(g4, d[bq], s.S2[bq]);
#pragma unroll
    for (int bq = 0; bq < 4; bq++) {
#pragma unroll
        for (int c = 0; c < 4; c++) {
            const float s3v = s.S3[bq * 4 + c];
#pragma unroll
            for (int e = 0; e < 4; e++) {
                float v = s.S4[bq * 16 + c * 4 + e];
                v = fmaf(s3v, d[e], v);
                v = fmaf(r[bq], h2[c * 4 + e], v);
                s.S4[bq * 16 + c * 4 + e] = v;
            }
        }
    }
    // level-3: S3 += S2 (x) e1 + (S1 + da/3) * h2
    const float g3 = fmaf(1.f / 3.f, da, s.S1);
#pragma unroll
    for (int bq = 0; bq < 4; bq++) {
        const float s2v = s.S2[bq];
#pragma unroll
        for (int c = 0; c < 4; c++) {
            float v = s.S3[bq * 4 + c];
            v = fmaf(s2v, d[c], v);
            v = fmaf(g3, h2[bq * 4 + c], v);
            s.S3[bq * 4 + c] = v;
        }
    }
    // level-2: S2 += (S1 + da/2) * d
    const float g2 = fmaf(0.5f, da, s.S1);
#pragma unroll
    for (int bq = 0; bq < 4; bq++) s.S2[bq] = fmaf(g2, d[bq], s.S2[bq]);
    s.S1 += da;
}

__device__ __forceinline__ float wred8(float v)
{
    v += __shfl_down_sync(0xffffffffu, v, 16);
    v += __shfl_down_sync(0xffffffffu, v, 8);
    v += __shfl_down_sync(0xffffffffu, v, 4);
    return v;
}

__global__ void __launch_bounds__(128) k_sig(const float* __restrict__ x)
{
    __shared__ float xs[INDIM];
    __shared__ float nvs[MDIM * 32];
    __shared__ float red[4 * SIGDIM];

    const int blk = blockIdx.x;
    const int b = blk >> 1, h = blk & 1;
    const int tid = threadIdx.x;

    for (int e = tid; e < INDIM; e += 128) xs[e] = x[b * INDIM + e];
    for (int e = tid; e < MDIM * 32; e += 128) {
        int i = e >> 5, kk = e & 31;
        nvs[e] = g_newV[(b * MDIM + i) * KPATH + h * 32 + kk];
    }
    __syncthreads();

    const int kk = tid >> 2;   // path within block (0..31)
    const int a  = tid & 3;    // tensor slice

    SigState s;
    s.S1 = 0.f;
#pragma unroll
    for (int i = 0; i < 4; i++) s.S2[i] = 0.f;
#pragma unroll
    for (int i = 0; i < 16; i++) s.S3[i] = 0.f;
#pragma unroll
    for (int i = 0; i < 64; i++) s.S4[i] = 0.f;

    // path: old0, new0, old1, new1, ..., old30, new30, old31
    float p0 = xs[0], p1 = xs[1], p2 = xs[2], p3 = xs[96];
    for (int m = 0; m < 31; m++) {
        // old m -> new m
        float q0 = nvs[(3 * m + 0) * 32 + kk];
        float q1 = nvs[(3 * m + 1) * 32 + kk];
        float q2 = nvs[(3 * m + 2) * 32 + kk];
        float qt = xs[128 + m];
        {
            float d[4] = { q0 - p0, q1 - p1, q2 - p2, qt - p3 };
            float da = (a == 0) ? d[0] : (a == 1) ? d[1] : (a == 2) ? d[2] : d[3];
            chen_step(s, d, da);
        }
        p0 = q0; p1 = q1; p2 = q2; p3 = qt;
        // new m -> old m+1
        q0 = xs[3 * (m + 1) + 0];
        q1 = xs[3 * (m + 1) + 1];
        q2 = xs[3 * (m + 1) + 2];
        qt = xs[96 + m + 1];
        {
            float d[4] = { q0 - p0, q1 - p1, q2 - p2, qt - p3 };
            float da = (a == 0) ? d[0] : (a == 1) ? d[1] : (a == 2) ? d[2] : d[3];
            chen_step(s, d, da);
        }
        p0 = q0; p1 = q1; p2 = q2; p3 = qt;
    }

    // per-path norms (reduce slice partials over the 4 lanes of this path)
    float n1 = s.S1 * s.S1;
    float n2 = 0.f, n3 = 0.f, n4 = 0.f;
#pragma unroll
    for (int i = 0; i < 4; i++)  n2 = fmaf(s.S2[i], s.S2[i], n2);
#pragma unroll
    for (int i = 0; i < 16; i++) n3 = fmaf(s.S3[i], s.S3[i], n3);
#pragma unroll
    for (int i = 0; i < 64; i++) n4 = fmaf(s.S4[i], s.S4[i], n4);
#pragma unroll
    for (int msk = 1; msk <= 2; msk <<= 1) {
        n1 += __shfl_xor_sync(0xffffffffu, n1, msk);
        n2 += __shfl_xor_sync(0xffffffffu, n2, msk);
        n3 += __shfl_xor_sync(0xffffffffu, n3, msk);
        n4 += __shfl_xor_sync(0xffffffffu, n4, msk);
    }
    const float norm2 = 1.f + n1 + n2 + n3 + n4;
    const float psi = (norm2 <= 4.f) ? norm2 : (8.f - 16.f / norm2);
    float lo = 0.f, hi = 1.f;
    for (int it = 0; it < 40; it++) {
        float mid = 0.5f * (lo + hi);
        float m2 = mid * mid, m4 = m2 * m2;
        float val = 1.f + m2 * n1 + m4 * n2 + (m4 * m2) * n3 + (m4 * m4) * n4;
        bool pos = val > psi;
        hi = pos ? mid : hi;
        lo = pos ? lo : mid;
    }
    const float lam = 0.5f * (lo + hi);
    const float l2 = lam * lam, l3 = l2 * lam, l4 = l2 * l2;
    s.S1 *= lam;
#pragma unroll
    for (int i = 0; i < 4; i++)  s.S2[i] *= l2;
#pragma unroll
    for (int i = 0; i < 16; i++) s.S3[i] *= l3;
#pragma unroll
    for (int i = 0; i < 64; i++) s.S4[i] *= l4;

    // reduce over the 8 paths of each warp; lanes 0..3 (= slice a) hold sums
    const int w = tid >> 5;
    const int lane = tid & 31;
    float v;
    v = wred8(s.S1);
    if (lane < 4) red[w * SIGDIM + a] = v;
#pragma unroll
    for (int j = 0; j < 4; j++) {
        v = wred8(s.S2[j]);
        if (lane < 4) red[w * SIGDIM + 4 + a * 4 + j] = v;
    }
#pragma unroll
    for (int j = 0; j < 16; j++) {
        v = wred8(s.S3[j]);
        if (lane < 4) red[w * SIGDIM + 20 + a * 16 + j] = v;
    }
#pragma unroll
    for (int j = 0; j < 64; j++) {
        v = wred8(s.S4[j]);
        if (lane < 4) red[w * SIGDIM + 84 + a * 64 + j] = v;
    }
    __syncthreads();
    for (int e = tid; e < SIGDIM; e += 128) {
        float sum = red[e] + red[SIGDIM + e] + red[2 * SIGDIM + e] + red[3 * SIGDIM + e];
        g_sigp[blk * SIGDIM + e] = sum;
    }
}

// ---------------------------------------------------------------------------
// Kernel 4: expected signature -> logits -> log_softmax
// One warp per batch element: lanes stride SIGDIM (coalesced g_sigp / Wf
// loads, Wf L2-resident), shfl-reduce the 10 logits, lane 0 writes output.
// ---------------------------------------------------------------------------
__global__ void __launch_bounds__(128) k_final(
    const float* __restrict__ Wf, const float* __restrict__ bf,
    float* __restrict__ out)
{
    const int warp = threadIdx.x >> 5;
    const int lane = threadIdx.x & 31;
    const int b = blockIdx.x * 4 + warp;

    float logit[10];
#pragma unroll
    for (int c = 0; c < 10; c++) logit[c] = 0.f;

    const float* sp0 = g_sigp + (2 * b) * SIGDIM;
    const float* sp1 = g_sigp + (2 * b + 1) * SIGDIM;
    for (int sidx = lane; sidx < SIGDIM; sidx += 32) {
        const float sv = (sp0[sidx] + sp1[sidx]) * (1.f / 64.f);
#pragma unroll
        for (int c = 0; c < 10; c++)
            logit[c] = fmaf(sv, Wf[c * SIGDIM + sidx], logit[c]);
    }
#pragma unroll
    for (int c = 0; c < 10; c++) {
#pragma unroll
        for (int off = 16; off >= 1; off >>= 1)
            logit[c] += __shfl_xor_sync(0xffffffffu, logit[c], off);
    }
    if (lane == 0) {
#pragma unroll
        for (int c = 0; c < 10; c++) logit[c] += bf[c];
        float mx = logit[0];
#pragma unroll
        for (int c = 1; c < 10; c++) mx = fmaxf(mx, logit[c]);
        float se = 0.f;
#pragma unroll
        for (int c = 0; c < 10; c++) se += expf(logit[c] - mx);
        const float lse = mx + logf(se);
#pragma unroll
        for (int c = 0; c < 10; c++) out[b * 10 + c] = logit[c] - lse;
    }
}

// ---------------------------------------------------------------------------
extern "C" void kernel_launch(void* const* d_in, const int* in_sizes, int n_in,
                              void* d_out, int out_size)
{
    const float* x   = (const float*)d_in[0];
    const float* Wm  = (const float*)d_in[1];
    const float* bm  = (const float*)d_in[2];
    const float* Wc  = (const float*)d_in[3];
    const float* bc  = (const float*)d_in[4];
    const float* Wf  = (const float*)d_in[5];
    const float* bf  = (const float*)d_in[6];
    const float* eps = (const float*)d_in[7];
    float* out = (float*)d_out;

    k_linear<<<dim3(24, 32), 128>>>(x, Wm, bm, Wc, bc);
    k_newv<<<BATCH, 256>>>(eps);
    k_sig<<<2 * BATCH, 128>>>(x);
    k_final<<<64, 128>>>(Wf, bf, out);
}

// round 5
// speedup vs baseline: 1.7377x; 1.2107x over previous
#include <cuda_runtime.h>

#define BATCH   256
#define INDIM   159
#define MDIM    93
#define MATEL   2976
#define LINDIM  (MDIM + MATEL)   /* 3069 */
#define KPATH   64
#define SIGDIM  340

typedef unsigned long long u64;

__device__ float g_lin[BATCH * LINDIM];
__device__ float g_newV[BATCH * MDIM * KPATH];
__device__ float g_lgt[2 * BATCH * 10];

// ---------------- packed f32x2 helpers (sm_100+ PTX) -----------------------
__device__ __forceinline__ u64 pk2(float lo, float hi) {
    u64 r; asm("mov.b64 %0, {%1, %2};" : "=l"(r) : "f"(lo), "f"(hi)); return r;
}
__device__ __forceinline__ u64 bc2(float x) {
    u64 r; asm("mov.b64 %0, {%1, %1};" : "=l"(r) : "f"(x)); return r;
}
__device__ __forceinline__ void unpk2(u64 p, float& lo, float& hi) {
    asm("mov.b64 {%0, %1}, %2;" : "=f"(lo), "=f"(hi) : "l"(p));
}
__device__ __forceinline__ u64 fma2(u64 a, u64 b, u64 c) {
    u64 d; asm("fma.rn.f32x2 %0, %1, %2, %3;" : "=l"(d) : "l"(a), "l"(b), "l"(c)); return d;
}
__device__ __forceinline__ u64 mul2(u64 a, u64 b) {
    u64 d; asm("mul.rn.f32x2 %0, %1, %2;" : "=l"(d) : "l"(a), "l"(b)); return d;
}

// ---------------------------------------------------------------------------
// Kernel 1: lin = x @ [W_mean; W_cov]^T + [b_mean; b_cov]
// ---------------------------------------------------------------------------
__global__ void __launch_bounds__(128) k_linear(
    const float* __restrict__ x,
    const float* __restrict__ Wm, const float* __restrict__ bm,
    const float* __restrict__ Wc, const float* __restrict__ bc)
{
    __shared__ float xs[8][INDIM];
    __shared__ float Ws[128][33];
    const int tid = threadIdx.x;
    const int b0  = blockIdx.y * 8;
    const int r0  = blockIdx.x * 128;

    for (int e = tid; e < 8 * INDIM; e += 128) {
        int bb = e / INDIM, c = e % INDIM;
        xs[bb][c] = x[(b0 + bb) * INDIM + c];
    }

    const int r = r0 + tid;
    float bias = 0.f;
    if (r < LINDIM) bias = (r < MDIM) ? bm[r] : bc[r - MDIM];
    float acc[8];
#pragma unroll
    for (int bb = 0; bb < 8; bb++) acc[bb] = bias;

    for (int ct = 0; ct < INDIM; ct += 32) {
        const int cn = min(32, INDIM - ct);
        __syncthreads();
        for (int e = tid; e < 128 * 32; e += 128) {
            int rr = e >> 5, cc = e & 31;
            int rg = r0 + rr;
            float w = 0.f;
            if (rg < LINDIM && cc < cn)
                w = (rg < MDIM) ? Wm[rg * INDIM + ct + cc]
                                : Wc[(rg - MDIM) * INDIM + ct + cc];
            Ws[rr][cc] = w;
        }
        __syncthreads();
        for (int cc = 0; cc < cn; cc++) {
            float w = Ws[tid][cc];
#pragma unroll
            for (int bb = 0; bb < 8; bb++)
                acc[bb] = fmaf(w, xs[bb][ct + cc], acc[bb]);
        }
    }
    if (r < LINDIM) {
#pragma unroll
        for (int bb = 0; bb < 8; bb++)
            g_lin[(b0 + bb) * LINDIM + r] = acc[bb];
    }
}

// ---------------------------------------------------------------------------
// Kernel 2: newV = band(M) @ eps + mean (closed-form band indexing)
// ---------------------------------------------------------------------------
__global__ void __launch_bounds__(256) k_newv(const float* __restrict__ eps)
{
    __shared__ float eps_s[MDIM * KPATH];
    __shared__ float cov_s[MATEL];
    __shared__ float mean_s[MDIM];
    const int b = blockIdx.x, tid = threadIdx.x;
    const float* lin = g_lin + b * LINDIM;

    for (int e = tid; e < MDIM * KPATH; e += 256)
        eps_s[e] = eps[b * MDIM * KPATH + e];
    for (int e = tid; e < MATEL; e += 256) cov_s[e] = lin[MDIM + e];
    for (int e = tid; e < MDIM; e += 256)  mean_s[e] = lin[e];
    __syncthreads();

    const int k  = tid & 63;
    const int i0 = tid >> 6;
    for (int i = i0; i < MDIM; i += 4) {
        const int X = i / 3, tr = i % 3;
        const int tbase = tr * (tr + 1) / 2;
        float acc = mean_s[i];
        for (int y = 0; y <= X; y++) {
            const int d = X - y;
            const int blk = (31 * d - (d * (d - 1)) / 2 + y) * 6 + tbase;
#pragma unroll
            for (int tc = 0; tc < 3; tc++) {
                if (tc <= tr)
                    acc = fmaf(cov_s[blk + tc], eps_s[(y * 3 + tc) * KPATH + k], acc);
            }
        }
        g_newV[(b * MDIM + i) * KPATH + k] = acc;
    }
}

// ---------------------------------------------------------------------------
// Kernel 3: signatures with f32x2-packed Chen recursion.
// 4 threads/path slice leading index a; per-thread state packs index bq in
// pairs j: S2p[j], S3p[j][c], S4p[j][c][e].
// ---------------------------------------------------------------------------
struct SigP {
    float S1;
    u64 S2p[2];
    u64 S3p[8];    // [j*4 + c]
    u64 S4p[32];   // [(j*4 + c)*4 + e]
};

__device__ __forceinline__ void chen_step_p(
    SigP& s, float d0, float d1, float d2, float d3, float da, u64 halfb)
{
    u64 db[4], dp[2];
    db[0] = bc2(d0); db[1] = bc2(d1); db[2] = bc2(d2); db[3] = bc2(d3);
    dp[0] = pk2(d0, d1); dp[1] = pk2(d2, d3);

    u64 hdb[4], hdp[2];
#pragma unroll
    for (int c = 0; c < 4; c++) hdb[c] = mul2(halfb, db[c]);
    hdp[0] = mul2(halfb, dp[0]); hdp[1] = mul2(halfb, dp[1]);

    // level 4: S4[bq][c][e] += (S3[bq][c] + (S2[bq]+g4*d[bq])*hd[c]) * d[e]
    const float g4 = fmaf(0.25f, da, s.S1) * (1.f / 3.f);
    const u64 g4b = bc2(g4);
    u64 rp[2];
    rp[0] = fma2(g4b, dp[0], s.S2p[0]);
    rp[1] = fma2(g4b, dp[1], s.S2p[1]);
#pragma unroll
    for (int j = 0; j < 2; j++) {
#pragma unroll
        for (int c = 0; c < 4; c++) {
            const u64 t = fma2(rp[j], hdb[c], s.S3p[j * 4 + c]);
#pragma unroll
            for (int e = 0; e < 4; e++)
                s.S4p[(j * 4 + c) * 4 + e] = fma2(t, db[e], s.S4p[(j * 4 + c) * 4 + e]);
        }
    }
    // level 3: S3[bq][c] += (S2[bq] + g3*hd[bq]) * d[c]
    const float g3 = fmaf(1.f / 3.f, da, s.S1);
    const u64 g3b = bc2(g3);
    u64 wp[2];
    wp[0] = fma2(g3b, hdp[0], s.S2p[0]);
    wp[1] = fma2(g3b, hdp[1], s.S2p[1]);
#pragma unroll
    for (int j = 0; j < 2; j++)
#pragma unroll
        for (int c = 0; c < 4; c++)
            s.S3p[j * 4 + c] = fma2(wp[j], db[c], s.S3p[j * 4 + c]);
    // level 2: S2[bq] += (S1 + da/2) * d[bq]
    const u64 g2b = bc2(fmaf(0.5f, da, s.S1));
    s.S2p[0] = fma2(g2b, dp[0], s.S2p[0]);
    s.S2p[1] = fma2(g2b, dp[1], s.S2p[1]);
    s.S1 += da;
}

__device__ __forceinline__ u64 wred8_2(u64 v)
{
    v = __shfl_down_sync(0xffffffffu, v, 16) + v;  // packed halves add separately?
    return v;
}

// packed 2-float add via f32x2 (shfl moves bits; add must be elementwise fp32)
__device__ __forceinline__ u64 add2(u64 a, u64 b) {
    u64 d; asm("add.rn.f32x2 %0, %1, %2;" : "=l"(d) : "l"(a), "l"(b)); return d;
}
__device__ __forceinline__ u64 wredp(u64 v)
{
    v = add2(v, __shfl_down_sync(0xffffffffu, v, 16));
    v = add2(v, __shfl_down_sync(0xffffffffu, v, 8));
    v = add2(v, __shfl_down_sync(0xffffffffu, v, 4));
    return v;
}

__global__ void __launch_bounds__(128, 3) k_sig(
    const float* __restrict__ x, const float* __restrict__ Wf)
{
    __shared__ float xs[INDIM];
    __shared__ float nvs[MDIM * 32];
    __shared__ float red[4 * SIGDIM];

    const int blk = blockIdx.x;
    const int b = blk >> 1, h = blk & 1;
    const int tid = threadIdx.x;

    for (int e = tid; e < INDIM; e += 128) xs[e] = x[b * INDIM + e];
    for (int e = tid; e < MDIM * 32; e += 128) {
        int i = e >> 5, kk = e & 31;
        nvs[e] = g_newV[(b * MDIM + i) * KPATH + h * 32 + kk];
    }
    __syncthreads();

    const int kk = tid >> 2;
    const int a  = tid & 3;
    const u64 halfb = bc2(0.5f);

    SigP s;
    s.S1 = 0.f;
    s.S2p[0] = s.S2p[1] = 0ull;
#pragma unroll
    for (int i = 0; i < 8; i++)  s.S3p[i] = 0ull;
#pragma unroll
    for (int i = 0; i < 32; i++) s.S4p[i] = 0ull;

    float p0 = xs[0], p1 = xs[1], p2 = xs[2], p3 = xs[96];
    for (int m = 0; m < 31; m++) {
        float q0 = nvs[(3 * m + 0) * 32 + kk];
        float q1 = nvs[(3 * m + 1) * 32 + kk];
        float q2 = nvs[(3 * m + 2) * 32 + kk];
        float qt = xs[128 + m];
        {
            float d0 = q0 - p0, d1 = q1 - p1, d2 = q2 - p2, d3 = qt - p3;
            float da = (a & 2) ? ((a & 1) ? d3 : d2) : ((a & 1) ? d1 : d0);
            chen_step_p(s, d0, d1, d2, d3, da, halfb);
        }
        p0 = q0; p1 = q1; p2 = q2; p3 = qt;
        q0 = xs[3 * (m + 1) + 0];
        q1 = xs[3 * (m + 1) + 1];
        q2 = xs[3 * (m + 1) + 2];
        qt = xs[96 + m + 1];
        {
            float d0 = q0 - p0, d1 = q1 - p1, d2 = q2 - p2, d3 = qt - p3;
            float da = (a & 2) ? ((a & 1) ? d3 : d2) : ((a & 1) ? d1 : d0);
            chen_step_p(s, d0, d1, d2, d3, da, halfb);
        }
        p0 = q0; p1 = q1; p2 = q2; p3 = qt;
    }

    // per-path norms (4 lanes of one path hold complementary slices)
    float n1 = s.S1 * s.S1;
    float n2 = 0.f, n3 = 0.f, n4 = 0.f;
#pragma unroll
    for (int i = 0; i < 2; i++)  { float lo, hi; unpk2(s.S2p[i], lo, hi); n2 = fmaf(lo, lo, n2); n2 = fmaf(hi, hi, n2); }
#pragma unroll
    for (int i = 0; i < 8; i++)  { float lo, hi; unpk2(s.S3p[i], lo, hi); n3 = fmaf(lo, lo, n3); n3 = fmaf(hi, hi, n3); }
#pragma unroll
    for (int i = 0; i < 32; i++) { float lo, hi; unpk2(s.S4p[i], lo, hi); n4 = fmaf(lo, lo, n4); n4 = fmaf(hi, hi, n4); }
#pragma unroll
    for (int msk = 1; msk <= 2; msk <<= 1) {
        n1 += __shfl_xor_sync(0xffffffffu, n1, msk);
        n2 += __shfl_xor_sync(0xffffffffu, n2, msk);
        n3 += __shfl_xor_sync(0xffffffffu, n3, msk);
        n4 += __shfl_xor_sync(0xffffffffu, n4, msk);
    }
    const float norm2 = 1.f + n1 + n2 + n3 + n4;
    const float psi = (norm2 <= 4.f) ? norm2 : (8.f - 16.f / norm2);
    float lo_ = 0.f, hi_ = 1.f;
    for (int it = 0; it < 40; it++) {
        float mid = 0.5f * (lo_ + hi_);
        float m2 = mid * mid, m4 = m2 * m2;
        float val = 1.f + m2 * n1 + m4 * n2 + (m4 * m2) * n3 + (m4 * m4) * n4;
        bool pos = val > psi;
        hi_ = pos ? mid : hi_;
        lo_ = pos ? lo_ : mid;
    }
    const float lam = 0.5f * (lo_ + hi_);
    const float l2 = lam * lam, l3 = l2 * lam, l4 = l2 * l2;
    s.S1 *= lam;
    const u64 l2b = bc2(l2), l3b = bc2(l3), l4b = bc2(l4);
#pragma unroll
    for (int i = 0; i < 2; i++)  s.S2p[i] = mul2(l2b, s.S2p[i]);
#pragma unroll
    for (int i = 0; i < 8; i++)  s.S3p[i] = mul2(l3b, s.S3p[i]);
#pragma unroll
    for (int i = 0; i < 32; i++) s.S4p[i] = mul2(l4b, s.S4p[i]);

    // reduce over the 8 paths of each warp; lanes 0..3 (= slice a) hold sums
    const int w = tid >> 5;
    const int lane = tid & 31;
    {
        float v = s.S1;
        v += __shfl_down_sync(0xffffffffu, v, 16);
        v += __shfl_down_sync(0xffffffffu, v, 8);
        v += __shfl_down_sync(0xffffffffu, v, 4);
        if (lane < 4) red[w * SIGDIM + a] = v;
    }
#pragma unroll
    for (int i = 0; i < 2; i++) {
        u64 v = wredp(s.S2p[i]);
        if (lane < 4) {
            float lo, hi; unpk2(v, lo, hi);
            red[w * SIGDIM + 4 + a * 4 + 2 * i]     = lo;
            red[w * SIGDIM + 4 + a * 4 + 2 * i + 1] = hi;
        }
    }
#pragma unroll
    for (int i = 0; i < 8; i++) {
        const int j = i >> 2, c = i & 3;
        u64 v = wredp(s.S3p[i]);
        if (lane < 4) {
            float lo, hi; unpk2(v, lo, hi);
            red[w * SIGDIM + 20 + a * 16 + (2 * j) * 4 + c]     = lo;
            red[w * SIGDIM + 20 + a * 16 + (2 * j + 1) * 4 + c] = hi;
        }
    }
#pragma unroll
    for (int i = 0; i < 32; i++) {
        const int j = i >> 4, c = (i >> 2) & 3, e = i & 3;
        u64 v = wredp(s.S4p[i]);
        if (lane < 4) {
            float lo, hi; unpk2(v, lo, hi);
            red[w * SIGDIM + 84 + a * 64 + (2 * j) * 16 + c * 4 + e]     = lo;
            red[w * SIGDIM + 84 + a * 64 + (2 * j + 1) * 16 + c * 4 + e] = hi;
        }
    }
    __syncthreads();
    // sum the 4 warp partials (in place: each e touched by exactly one thread)
    for (int e = tid; e < SIGDIM; e += 128)
        red[e] = red[e] + red[SIGDIM + e] + red[2 * SIGDIM + e] + red[3 * SIGDIM + e];
    __syncthreads();

    // partial logits for this block's 32 paths (deterministic, no atomics)
    for (int c = w; c < 10; c += 4) {
        float acc = 0.f;
        for (int sidx = lane; sidx < SIGDIM; sidx += 32)
            acc = fmaf(red[sidx], Wf[c * SIGDIM + sidx], acc);
#pragma unroll
        for (int off = 16; off >= 1; off >>= 1)
            acc += __shfl_xor_sync(0xffffffffu, acc, off);
        if (lane == 0) g_lgt[blk * 10 + c] = acc;
    }
}

// ---------------------------------------------------------------------------
// Kernel 4: combine partial logits, log_softmax. One warp per batch element.
// ---------------------------------------------------------------------------
__global__ void __launch_bounds__(128) k_final(
    const float* __restrict__ bf, float* __restrict__ out)
{
    const int warp = threadIdx.x >> 5;
    const int lane = threadIdx.x & 31;
    const int b = blockIdx.x * 4 + warp;

    float v = -3.0e38f;
    if (lane < 10)
        v = (g_lgt[(2 * b) * 10 + lane] + g_lgt[(2 * b + 1) * 10 + lane]) * (1.f / 64.f)
            + bf[lane];
    float mx = v;
#pragma unroll
    for (int off = 16; off >= 1; off >>= 1)
        mx = fmaxf(mx, __shfl_xor_sync(0xffffffffu, mx, off));
    float ex = (lane < 10) ? expf(v - mx) : 0.f;
    float se = ex;
#pragma unroll
    for (int off = 16; off >= 1; off >>= 1)
        se += __shfl_xor_sync(0xffffffffu, se, off);
    const float lse = mx + logf(se);
    if (lane < 10) out[b * 10 + lane] = v - lse;
}

// ---------------------------------------------------------------------------
extern "C" void kernel_launch(void* const* d_in, const int* in_sizes, int n_in,
                              void* d_out, int out_size)
{
    const float* x   = (const float*)d_in[0];
    const float* Wm  = (const float*)d_in[1];
    const float* bm  = (const float*)d_in[2];
    const float* Wc  = (const float*)d_in[3];
    const float* bc  = (const float*)d_in[4];
    const float* Wf  = (const float*)d_in[5];
    const float* bf  = (const float*)d_in[6];
    const float* eps = (const float*)d_in[7];
    float* out = (float*)d_out;

    k_linear<<<dim3(24, 32), 128>>>(x, Wm, bm, Wc, bc);
    k_newv<<<BATCH, 256>>>(eps);
    k_sig<<<2 * BATCH, 128>>>(x, Wf);
    k_final<<<64, 128>>>(bf, out);
}

// round 6
// speedup vs baseline: 1.8855x; 1.0850x over previous
#include <cuda_runtime.h>

#define BATCH   256
#define INDIM   159
#define MDIM    93
#define MATEL   2976
#define LINDIM  (MDIM + MATEL)   /* 3069 */
#define KPATH   64
#define SIGDIM  340

typedef unsigned long long u64;

__device__ float g_lin[BATCH * LINDIM];
__device__ float g_lgt[2 * BATCH * 10];
__device__ int   g_cnt[BATCH];          // zero-init (.bss); restored to 0 each run

// ---------------- packed f32x2 helpers (sm_100+ PTX) -----------------------
__device__ __forceinline__ u64 pk2(float lo, float hi) {
    u64 r; asm("mov.b64 %0, {%1, %2};" : "=l"(r) : "f"(lo), "f"(hi)); return r;
}
__device__ __forceinline__ u64 bc2(float x) {
    u64 r; asm("mov.b64 %0, {%1, %1};" : "=l"(r) : "f"(x)); return r;
}
__device__ __forceinline__ void unpk2(u64 p, float& lo, float& hi) {
    asm("mov.b64 {%0, %1}, %2;" : "=f"(lo), "=f"(hi) : "l"(p));
}
__device__ __forceinline__ u64 fma2(u64 a, u64 b, u64 c) {
    u64 d; asm("fma.rn.f32x2 %0, %1, %2, %3;" : "=l"(d) : "l"(a), "l"(b), "l"(c)); return d;
}
__device__ __forceinline__ u64 mul2(u64 a, u64 b) {
    u64 d; asm("mul.rn.f32x2 %0, %1, %2;" : "=l"(d) : "l"(a), "l"(b)); return d;
}
__device__ __forceinline__ u64 add2(u64 a, u64 b) {
    u64 d; asm("add.rn.f32x2 %0, %1, %2;" : "=l"(d) : "l"(a), "l"(b)); return d;
}

// ---------------------------------------------------------------------------
// Kernel 1: lin = x @ [W_mean; W_cov]^T + bias.  16-batch tiles, transposed x
// staging, f32x2 inner loop (8 batch-pairs per thread-row).
// ---------------------------------------------------------------------------
__global__ void __launch_bounds__(128) k_linear(
    const float* __restrict__ x,
    const float* __restrict__ Wm, const float* __restrict__ bm,
    const float* __restrict__ Wc, const float* __restrict__ bc)
{
    __shared__ float xt[INDIM][20];     // transposed, 80B row stride (16B aligned)
    __shared__ float Ws[128][33];
    const int tid = threadIdx.x;
    const int b0  = blockIdx.y * 16;
    const int r0  = blockIdx.x * 128;

    for (int e = tid; e < 16 * INDIM; e += 128) {
        int bb = e / INDIM, c = e % INDIM;
        xt[c][bb] = x[(b0 + bb) * INDIM + c];
    }

    const int r = r0 + tid;
    float bias = 0.f;
    if (r < LINDIM) bias = (r < MDIM) ? bm[r] : bc[r - MDIM];
    u64 acc2[8];
    const u64 biasb = bc2(bias);
#pragma unroll
    for (int p = 0; p < 8; p++) acc2[p] = (p == 0) ? biasb : bc2(0.f);

    for (int ct = 0; ct < INDIM; ct += 32) {
        const int cn = min(32, INDIM - ct);
        __syncthreads();
        for (int e = tid; e < 128 * 32; e += 128) {
            int rr = e >> 5, cc = e & 31;
            int rg = r0 + rr;
            float w = 0.f;
            if (rg < LINDIM && cc < cn)
                w = (rg < MDIM) ? Wm[rg * INDIM + ct + cc]
                                : Wc[(rg - MDIM) * INDIM + ct + cc];
            Ws[rr][cc] = w;
        }
        __syncthreads();
        for (int cc = 0; cc < cn; cc++) {
            const u64 w2 = bc2(Ws[tid][cc]);
            const u64* xp = (const u64*)&xt[ct + cc][0];
#pragma unroll
            for (int p = 0; p < 8; p++) acc2[p] = fma2(w2, xp[p], acc2[p]);
        }
    }
    if (r < LINDIM) {
#pragma unroll
        for (int p = 0; p < 8; p++) {
            float lo, hi; unpk2(acc2[p], lo, hi);
            g_lin[(b0 + 2 * p) * LINDIM + r]     = lo;
            g_lin[(b0 + 2 * p + 1) * LINDIM + r] = hi;
        }
    }
}

// ---------------------------------------------------------------------------
// Kernel 2 (fused): newV (band matvec) + signatures + normalization + partial
// logits + inline final softmax via arrival counter.  Grid 2*BATCH x 128.
// ---------------------------------------------------------------------------
struct SigP {
    float S1;
    u64 S2p[2];
    u64 S3p[8];    // [j*4 + c]
    u64 S4p[32];   // [(j*4 + c)*4 + e]
};

__device__ __forceinline__ void chen_step_p(
    SigP& s, float d0, float d1, float d2, float d3, float da, u64 halfb)
{
    u64 db[4], dp[2];
    db[0] = bc2(d0); db[1] = bc2(d1); db[2] = bc2(d2); db[3] = bc2(d3);
    dp[0] = pk2(d0, d1); dp[1] = pk2(d2, d3);

    // level 4: S4[bq][c][e] += (S3[bq][c] + (0.5*r[bq])*d[c]) * d[e]
    //   where r[bq] = S2[bq] + g4*d[bq];  (x*0.5 is exact -> identical rounding)
    const float g4 = fmaf(0.25f, da, s.S1) * (1.f / 3.f);
    const u64 g4b = bc2(g4);
    u64 rph[2];
    rph[0] = mul2(halfb, fma2(g4b, dp[0], s.S2p[0]));
    rph[1] = mul2(halfb, fma2(g4b, dp[1], s.S2p[1]));
#pragma unroll
    for (int j = 0; j < 2; j++) {
#pragma unroll
        for (int c = 0; c < 4; c++) {
            const u64 t = fma2(rph[j], db[c], s.S3p[j * 4 + c]);
#pragma unroll
            for (int e = 0; e < 4; e++)
                s.S4p[(j * 4 + c) * 4 + e] = fma2(t, db[e], s.S4p[(j * 4 + c) * 4 + e]);
        }
    }
    // level 3: S3[bq][c] += (S2[bq] + (0.5*g3)*d[bq]) * d[c]
    const float g3h = 0.5f * fmaf(1.f / 3.f, da, s.S1);
    const u64 g3hb = bc2(g3h);
    u64 wp[2];
    wp[0] = fma2(g3hb, dp[0], s.S2p[0]);
    wp[1] = fma2(g3hb, dp[1], s.S2p[1]);
#pragma unroll
    for (int j = 0; j < 2; j++)
#pragma unroll
        for (int c = 0; c < 4; c++)
            s.S3p[j * 4 + c] = fma2(wp[j], db[c], s.S3p[j * 4 + c]);
    // level 2
    const u64 g2b = bc2(fmaf(0.5f, da, s.S1));
    s.S2p[0] = fma2(g2b, dp[0], s.S2p[0]);
    s.S2p[1] = fma2(g2b, dp[1], s.S2p[1]);
    s.S1 += da;
}

__device__ __forceinline__ u64 wredp(u64 v)
{
    v = add2(v, __shfl_down_sync(0xffffffffu, v, 16));
    v = add2(v, __shfl_down_sync(0xffffffffu, v, 8));
    v = add2(v, __shfl_down_sync(0xffffffffu, v, 4));
    return v;
}

__global__ void __launch_bounds__(128, 3) k_sigf(
    const float* __restrict__ x, const float* __restrict__ eps,
    const float* __restrict__ Wf, const float* __restrict__ bf,
    float* __restrict__ out)
{
    __shared__ float xs[INDIM];
    __shared__ float covm[LINDIM];          // mean [0:93), cov [93:3069)
    __shared__ float nvs[MDIM * 32];
    __shared__ float eps_red[MDIM * 32];    // eps slice; re-used as red[4*SIGDIM]
    __shared__ int   arrive_s;

    const int blk = blockIdx.x;
    const int b = blk >> 1, h = blk & 1;
    const int tid = threadIdx.x;

    for (int e = tid; e < INDIM; e += 128) xs[e] = x[b * INDIM + e];
    for (int e = tid; e < LINDIM; e += 128) covm[e] = g_lin[b * LINDIM + e];
    for (int e = tid; e < MDIM * 32; e += 128) {
        int j = e >> 5, kk = e & 31;
        eps_red[e] = eps[(b * MDIM + j) * KPATH + h * 32 + kk];
    }
    __syncthreads();

    // ---- newV for this block's 32 k's (f32x2 over k-pairs) ----
    {
        const int kp = tid & 15;        // k-pair 0..15 (k = 2kp, 2kp+1)
        const int ig = tid >> 4;        // 0..7
        for (int i = ig; i < MDIM; i += 8) {
            const int X = i / 3, tr = i % 3;
            const int tbase = 93 + tr * (tr + 1) / 2;
            u64 acc = bc2(covm[i]);
            for (int y = 0; y <= X; y++) {
                const int d = X - y;
                const int blk6 = (31 * d - (d * (d - 1)) / 2 + y) * 6 + tbase;
#pragma unroll
                for (int tc = 0; tc < 3; tc++) {
                    if (tc <= tr) {
                        const u64 ep = *(const u64*)&eps_red[(y * 3 + tc) * 32 + 2 * kp];
                        acc = fma2(bc2(covm[blk6 + tc]), ep, acc);
                    }
                }
            }
            *(u64*)&nvs[i * 32 + 2 * kp] = acc;
        }
    }
    __syncthreads();

    // ---- signature recursion ----
    const int kk = tid >> 2;
    const int a  = tid & 3;
    const u64 halfb = bc2(0.5f);

    SigP s;
    s.S1 = 0.f;
    s.S2p[0] = s.S2p[1] = 0ull;
#pragma unroll
    for (int i = 0; i < 8; i++)  s.S3p[i] = 0ull;
#pragma unroll
    for (int i = 0; i < 32; i++) s.S4p[i] = 0ull;

    float p0 = xs[0], p1 = xs[1], p2 = xs[2], p3 = xs[96];
    for (int m = 0; m < 31; m++) {
        float q0 = nvs[(3 * m + 0) * 32 + kk];
        float q1 = nvs[(3 * m + 1) * 32 + kk];
        float q2 = nvs[(3 * m + 2) * 32 + kk];
        float qt = xs[128 + m];
        {
            float d0 = q0 - p0, d1 = q1 - p1, d2 = q2 - p2, d3 = qt - p3;
            float da = (a & 2) ? ((a & 1) ? d3 : d2) : ((a & 1) ? d1 : d0);
            chen_step_p(s, d0, d1, d2, d3, da, halfb);
        }
        p0 = q0; p1 = q1; p2 = q2; p3 = qt;
        q0 = xs[3 * (m + 1) + 0];
        q1 = xs[3 * (m + 1) + 1];
        q2 = xs[3 * (m + 1) + 2];
        qt = xs[96 + m + 1];
        {
            float d0 = q0 - p0, d1 = q1 - p1, d2 = q2 - p2, d3 = qt - p3;
            float da = (a & 2) ? ((a & 1) ? d3 : d2) : ((a & 1) ? d1 : d0);
            chen_step_p(s, d0, d1, d2, d3, da, halfb);
        }
        p0 = q0; p1 = q1; p2 = q2; p3 = qt;
    }

    // ---- per-path norms + bisection ----
    float n1 = s.S1 * s.S1;
    float n2 = 0.f, n3 = 0.f, n4 = 0.f;
#pragma unroll
    for (int i = 0; i < 2; i++)  { float lo, hi; unpk2(s.S2p[i], lo, hi); n2 = fmaf(lo, lo, n2); n2 = fmaf(hi, hi, n2); }
#pragma unroll
    for (int i = 0; i < 8; i++)  { float lo, hi; unpk2(s.S3p[i], lo, hi); n3 = fmaf(lo, lo, n3); n3 = fmaf(hi, hi, n3); }
#pragma unroll
    for (int i = 0; i < 32; i++) { float lo, hi; unpk2(s.S4p[i], lo, hi); n4 = fmaf(lo, lo, n4); n4 = fmaf(hi, hi, n4); }
#pragma unroll
    for (int msk = 1; msk <= 2; msk <<= 1) {
        n1 += __shfl_xor_sync(0xffffffffu, n1, msk);
        n2 += __shfl_xor_sync(0xffffffffu, n2, msk);
        n3 += __shfl_xor_sync(0xffffffffu, n3, msk);
        n4 += __shfl_xor_sync(0xffffffffu, n4, msk);
    }
    const float norm2 = 1.f + n1 + n2 + n3 + n4;
    const float psi = (norm2 <= 4.f) ? norm2 : (8.f - 16.f / norm2);
    float lo_ = 0.f, hi_ = 1.f;
    for (int it = 0; it < 40; it++) {
        float mid = 0.5f * (lo_ + hi_);
        float m2 = mid * mid, m4 = m2 * m2;
        float val = 1.f + m2 * n1 + m4 * n2 + (m4 * m2) * n3 + (m4 * m4) * n4;
        bool pos = val > psi;
        hi_ = pos ? mid : hi_;
        lo_ = pos ? lo_ : mid;
    }
    const float lam = 0.5f * (lo_ + hi_);
    const float l2 = lam * lam, l3 = l2 * lam, l4 = l2 * l2;
    s.S1 *= lam;
    const u64 l2b = bc2(l2), l3b = bc2(l3), l4b = bc2(l4);
#pragma unroll
    for (int i = 0; i < 2; i++)  s.S2p[i] = mul2(l2b, s.S2p[i]);
#pragma unroll
    for (int i = 0; i < 8; i++)  s.S3p[i] = mul2(l3b, s.S3p[i]);
#pragma unroll
    for (int i = 0; i < 32; i++) s.S4p[i] = mul2(l4b, s.S4p[i]);

    // ---- reduce the 8 paths of each warp into red = eps_red (re-used) ----
    __syncthreads();                 // eps no longer needed
    float* red = eps_red;
    const int w = tid >> 5;
    const int lane = tid & 31;
    {
        float v = s.S1;
        v += __shfl_down_sync(0xffffffffu, v, 16);
        v += __shfl_down_sync(0xffffffffu, v, 8);
        v += __shfl_down_sync(0xffffffffu, v, 4);
        if (lane < 4) red[w * SIGDIM + a] = v;
    }
#pragma unroll
    for (int i = 0; i < 2; i++) {
        u64 v = wredp(s.S2p[i]);
        if (lane < 4) {
            float lo, hi; unpk2(v, lo, hi);
            red[w * SIGDIM + 4 + a * 4 + 2 * i]     = lo;
            red[w * SIGDIM + 4 + a * 4 + 2 * i + 1] = hi;
        }
    }
#pragma unroll
    for (int i = 0; i < 8; i++) {
        const int j = i >> 2, c = i & 3;
        u64 v = wredp(s.S3p[i]);
        if (lane < 4) {
            float lo, hi; unpk2(v, lo, hi);
            red[w * SIGDIM + 20 + a * 16 + (2 * j) * 4 + c]     = lo;
            red[w * SIGDIM + 20 + a * 16 + (2 * j + 1) * 4 + c] = hi;
        }
    }
#pragma unroll
    for (int i = 0; i < 32; i++) {
        const int j = i >> 4, c = (i >> 2) & 3, e = i & 3;
        u64 v = wredp(s.S4p[i]);
        if (lane < 4) {
            float lo, hi; unpk2(v, lo, hi);
            red[w * SIGDIM + 84 + a * 64 + (2 * j) * 16 + c * 4 + e]     = lo;
            red[w * SIGDIM + 84 + a * 64 + (2 * j + 1) * 16 + c * 4 + e] = hi;
        }
    }
    __syncthreads();
    for (int e = tid; e < SIGDIM; e += 128)
        red[e] = red[e] + red[SIGDIM + e] + red[2 * SIGDIM + e] + red[3 * SIGDIM + e];
    __syncthreads();

    // ---- partial logits for this half-batch ----
    for (int c = w; c < 10; c += 4) {
        float acc = 0.f;
        for (int sidx = lane; sidx < SIGDIM; sidx += 32)
            acc = fmaf(red[sidx], Wf[c * SIGDIM + sidx], acc);
#pragma unroll
        for (int off = 16; off >= 1; off >>= 1)
            acc += __shfl_xor_sync(0xffffffffu, acc, off);
        if (lane == 0) g_lgt[blk * 10 + c] = acc;
    }
    __syncthreads();

    // ---- arrival counter: second block for this b does the softmax ----
    if (tid == 0) {
        __threadfence();
        arrive_s = atomicAdd(&g_cnt[b], 1);
    }
    __syncthreads();
    if (arrive_s == 1 && w == 0) {
        __threadfence();
        float v = -3.0e38f;
        if (lane < 10)
            v = (g_lgt[(2 * b) * 10 + lane] + g_lgt[(2 * b + 1) * 10 + lane])
                * (1.f / 64.f) + bf[lane];
        float mx = v;
#pragma unroll
        for (int off = 16; off >= 1; off >>= 1)
            mx = fmaxf(mx, __shfl_xor_sync(0xffffffffu, mx, off));
        float ex = (lane < 10) ? expf(v - mx) : 0.f;
        float se = ex;
#pragma unroll
        for (int off = 16; off >= 1; off >>= 1)
            se += __shfl_xor_sync(0xffffffffu, se, off);
        const float lse = mx + logf(se);
        if (lane < 10) out[b * 10 + lane] = v - lse;
        if (lane == 0) g_cnt[b] = 0;   // restore for next graph replay
    }
}

// ---------------------------------------------------------------------------
extern "C" void kernel_launch(void* const* d_in, const int* in_sizes, int n_in,
                              void* d_out, int out_size)
{
    const float* x   = (const float*)d_in[0];
    const float* Wm  = (const float*)d_in[1];
    const float* bm  = (const float*)d_in[2];
    const float* Wc  = (const float*)d_in[3];
    const float* bc  = (const float*)d_in[4];
    const float* Wf  = (const float*)d_in[5];
    const float* bf  = (const float*)d_in[6];
    const float* eps = (const float*)d_in[7];
    float* out = (float*)d_out;

    k_linear<<<dim3(24, 16), 128>>>(x, Wm, bm, Wc, bc);
    k_sigf<<<2 * BATCH, 128>>>(x, eps, Wf, bf, out);
}